// round 11
// baseline (speedup 1.0000x reference)
#include <cuda_runtime.h>
#include <cuda_fp16.h>
#include <cstdint>

// ============================ problem constants ============================
#define NROWS 16384
#define MCOLS 4096
#define DDIM  128
#define BI    128            // rows per CTA
#define KT    64             // j per pipeline stage
#define NKT   (MCOLS / KT)   // 64 stages
#define THREADS 512          // 8 consumer + 8 producer warps
#define NSTG 3               // ring depth
#define LOOKAHEAD 2          // fetch distance (stages)

// A/B pitch: 64 fp16 (128B) + 16B pad = 144 -> conflict-free ldmatrix
#define PITCH 144
// mask pitch: 64 ints (256B) + 16B pad
#define PITCHM 272

// ring-stage layout (bytes, from 16B-aligned smem base)
#define A_OFF  0             // 128 x 144 = 18432
#define B_OFF  18432         // 128 x 144 = 18432
#define MK_OFF 36864         // 128 x 272 = 34816
#define RE_OFF 71680         // 8 producer-warp copies x 512B = 4096
#define STG    75776         // stage stride
#define ZS_OFF (NSTG * STG)  // 227328: 128 floats
#define SMEM_BYTES (ZS_OFF + 512)

// named barriers: FULL(s)=1+s (1-3), FREE(s)=4+s (4-6), Z-ready=7
#define BAR_SYNC(id)   asm volatile("bar.sync %0, %1;"   :: "r"(id), "r"(THREADS) : "memory")
#define BAR_ARRIVE(id) asm volatile("bar.arrive %0, %1;" :: "r"(id), "r"(THREADS) : "memory")

// ============================ device scratch ===============================
__device__ float g_c[NROWS];    // exp(s_i)
__device__ float g_dd[NROWS];   // exp(0.2 s_i)
__device__ float g_r[MCOLS];    // exp(-0.8 t_j)
__device__ float g_et[MCOLS];   // exp(t_j)
__device__ __half g_UTh[(size_t)DDIM * MCOLS]; // U^T[d][j] = fp16(exp(t_j)*V[j][d])

// ============================ asm helpers ==================================
__device__ __forceinline__ uint32_t smem_to_u32(const void* p) {
    uint32_t a;
    asm("{ .reg .u64 t; cvta.to.shared.u64 t, %1; cvt.u32.u64 %0, t; }"
        : "=r"(a) : "l"(p));
    return a;
}

#define LDM4(r0, r1, r2, r3, addr) \
    asm volatile("ldmatrix.sync.aligned.m8n8.x4.shared.b16 {%0,%1,%2,%3}, [%4];" \
        : "=r"(r0), "=r"(r1), "=r"(r2), "=r"(r3) : "r"(addr))

#define MMA_F16(d, a, b) \
    asm volatile("mma.sync.aligned.m16n8k16.row.col.f32.f16.f16.f32 " \
        "{%0,%1,%2,%3}, {%4,%5,%6,%7}, {%8,%9}, {%0,%1,%2,%3};" \
        : "+f"((d)[0]), "+f"((d)[1]), "+f"((d)[2]), "+f"((d)[3]) \
        : "r"((a)[0]), "r"((a)[1]), "r"((a)[2]), "r"((a)[3]), \
          "r"((b)[0]), "r"((b)[1]))

#define CP_ASYNC16(dst, src) \
    asm volatile("cp.async.cg.shared.global [%0], [%1], 16;" :: "r"(dst), "l"(src))
#define CP_COMMIT()  asm volatile("cp.async.commit_group;" ::: "memory")
#define CP_WAIT1()   asm volatile("cp.async.wait_group 1;" ::: "memory")

// ============================ prep kernels =================================
// fused: rows [0,NROWS) -> self scalars, rows [NROWS,NROWS+MCOLS) -> neigh
__global__ void prep_scalars(const float* __restrict__ sf,
                             const float* __restrict__ fn,
                             const float* __restrict__ a) {
    int row = blockIdx.x * 8 + (threadIdx.x >> 5);
    int lane = threadIdx.x & 31;
    const bool is_self = row < NROWS;
    const float* src = is_self ? &sf[(size_t)row * DDIM]
                               : &fn[(size_t)(row - NROWS) * DDIM];
    const float* w   = is_self ? a : a + DDIM;
    float4 f = *(const float4*)&src[lane * 4];
    float4 ww = *(const float4*)&w[lane * 4];
    float v = f.x * ww.x + f.y * ww.y + f.z * ww.z + f.w * ww.w;
    #pragma unroll
    for (int o = 16; o > 0; o >>= 1) v += __shfl_xor_sync(0xffffffffu, v, o);
    if (lane == 0) {
        if (is_self) {
            g_c[row]  = expf(v);
            g_dd[row] = expf(0.2f * v);
        } else {
            int j = row - NROWS;
            g_r[j]  = expf(-0.8f * v);
            g_et[j] = expf(v);
        }
    }
}

__global__ void prep_ut(const float* __restrict__ fn) {
    int j = blockIdx.x * 256 + threadIdx.x;
    int d = blockIdx.y;
    float v = g_et[j] * fn[(size_t)j * DDIM + d];
    g_UTh[(size_t)d * MCOLS + j] = __float2half_rn(v);
}

// ============================ main kernel ==================================
// A = mask ? max(c_i, dd_i * r_j) : 0   (leaky branch: s+t>0 <=> c > dd*r).
// Stored fp16 RN; Z accumulated in f32 (RN rounding is unbiased -> consistent).
__device__ __forceinline__ float aval(int m, float rr, float cc, float dd) {
    float v = fmaxf(cc, dd * rr);
    return m ? v : 0.0f;
}

// fetch one stage: masks for this thread's OWN build rows/cols, B tile, RE
__device__ __forceinline__ void fetch_stage(uint32_t smb,
                                            const char* mrow0, const char* mrow1,
                                            const __half* brow, int kt, int s,
                                            int r0, int jc, int frow, int fh,
                                            int pw, int lane) {
    const uint32_t base = smb + s * STG;
    // masks: rows r0, r0+1; 16 j's (64B) at column chunk jc
    uint32_t mdst = base + MK_OFF + r0 * PITCHM + jc * 64u;
    const char* ms0 = mrow0 + (size_t)kt * 256 + jc * 64;
    const char* ms1 = mrow1 + (size_t)kt * 256 + jc * 64;
    #pragma unroll
    for (int u = 0; u < 4; u++) {
        CP_ASYNC16(mdst + u * 16,          ms0 + u * 16);
        CP_ASYNC16(mdst + PITCHM + u * 16, ms1 + u * 16);
    }
    // B: U^T d-row frow, 32-j half fh (64B)
    uint32_t bdst = base + B_OFF + frow * PITCH + fh * 64u;
    const __half* bsrc = brow + kt * KT;   // brow already offset by fh*32
    #pragma unroll
    for (int u = 0; u < 4; u++)
        CP_ASYNC16(bdst + u * 16, bsrc + u * 8);
    // r, e consts: per-producer-warp copy (512B: r 256B then e 256B)
    {
        const float* cbase = (lane < 16) ? g_r : g_et;
        const int q = lane & 15;
        CP_ASYNC16(base + RE_OFF + pw * 512u + (uint32_t)lane * 16u,
                   cbase + kt * KT + q * 4);
    }
}

__global__ void __launch_bounds__(THREADS, 1)
attn_main(const int* __restrict__ nm, float* __restrict__ out) {
    extern __shared__ char sm[];
    const uint32_t smb = smem_to_u32(sm);
    const int tid = threadIdx.x, lane = tid & 31, wid = tid >> 5;
    const int blockRow = blockIdx.x * BI;
    float* zsm = (float*)(sm + ZS_OFF);

    if (wid >= 8) {
        // ========================= PRODUCER (warps 8-15) =========================
        const int tp = tid - 256;
        const int pw = tp >> 5;                    // producer warp 0-7
        const int frow = tp >> 1, fh = tp & 1;     // B fetch: d-row, 32-j half
        const int r0 = (tp >> 2) * 2, jc = tp & 3; // rows r0,r0+1; 16-j chunk jc
        const float cc0 = g_c[blockRow + r0],  cc1 = g_c[blockRow + r0 + 1];
        const float dd0 = g_dd[blockRow + r0], dd1 = g_dd[blockRow + r0 + 1];
        float z0 = 0.0f, z1 = 0.0f;

        const char* mrow0 = (const char*)(nm + (size_t)(blockRow + r0) * MCOLS);
        const char* mrow1 = (const char*)(nm + (size_t)(blockRow + r0 + 1) * MCOLS);
        const __half* brow = g_UTh + (size_t)frow * MCOLS + fh * 32;

        // prologue: stage LOOKAHEAD stages (one commit group per stage)
        #pragma unroll
        for (int k0 = 0; k0 < LOOKAHEAD; k0++) {
            fetch_stage(smb, mrow0, mrow1, brow, k0, k0, r0, jc, frow, fh, pw, lane);
            CP_COMMIT();
        }

        int s = 0;
        for (int kt = 0; kt < NKT; kt++) {
            // one commit per stage: allowing 1 newest outstanding => fetch(kt) done
            CP_WAIT1();
            __syncwarp();   // publish this warp's RE copy across its lanes

            // ---- build A(kt) into slot s from smem masks (own fetches) ----
            {
                const float4* re = (const float4*)(sm + s * STG + RE_OFF + pw * 512);
                const char* mks = sm + s * STG + MK_OFF + r0 * PITCHM + jc * 64;
                char* dst = sm + s * STG + A_OFF + r0 * PITCH + jc * 32;
                float4 rr[4], ee[4];
                #pragma unroll
                for (int q = 0; q < 4; q++) {
                    rr[q] = re[jc * 4 + q];
                    ee[q] = re[16 + jc * 4 + q];
                }
                #pragma unroll
                for (int i = 0; i < 2; i++) {
                    const float cc = i ? cc1 : cc0, dd = i ? dd1 : dd0;
                    float av[16];
                    float z = 0.0f;
                    #pragma unroll
                    for (int u = 0; u < 4; u++) {
                        const int4 m = *(const int4*)(mks + i * PITCHM + u * 16);
                        av[u * 4 + 0] = aval(m.x, rr[u].x, cc, dd);
                        av[u * 4 + 1] = aval(m.y, rr[u].y, cc, dd);
                        av[u * 4 + 2] = aval(m.z, rr[u].z, cc, dd);
                        av[u * 4 + 3] = aval(m.w, rr[u].w, cc, dd);
                        z += av[u * 4 + 0] * ee[u].x + av[u * 4 + 1] * ee[u].y
                           + av[u * 4 + 2] * ee[u].z + av[u * 4 + 3] * ee[u].w;
                    }
                    if (i) z1 += z; else z0 += z;
                    uint4 q0, q1;
                    __half2 h;
                    h = __floats2half2_rn(av[0],  av[1]);  q0.x = *(uint32_t*)&h;
                    h = __floats2half2_rn(av[2],  av[3]);  q0.y = *(uint32_t*)&h;
                    h = __floats2half2_rn(av[4],  av[5]);  q0.z = *(uint32_t*)&h;
                    h = __floats2half2_rn(av[6],  av[7]);  q0.w = *(uint32_t*)&h;
                    h = __floats2half2_rn(av[8],  av[9]);  q1.x = *(uint32_t*)&h;
                    h = __floats2half2_rn(av[10], av[11]); q1.y = *(uint32_t*)&h;
                    h = __floats2half2_rn(av[12], av[13]); q1.z = *(uint32_t*)&h;
                    h = __floats2half2_rn(av[14], av[15]); q1.w = *(uint32_t*)&h;
                    *(uint4*)(dst + i * PITCH)      = q0;
                    *(uint4*)(dst + i * PITCH + 16) = q1;
                }
            }
            BAR_ARRIVE(1 + s);                       // FULL(s)

            const int kf = kt + LOOKAHEAD;
            if (kf < NKT) {
                int s2 = s + LOOKAHEAD; if (s2 >= NSTG) s2 -= NSTG;
                if (kf >= NSTG) BAR_SYNC(4 + s2);    // consumers freed slot s2
                fetch_stage(smb, mrow0, mrow1, brow, kf, s2, r0, jc, frow, fh, pw, lane);
            }
            CP_COMMIT();                             // one group per stage, always
            s = (s + 1 == NSTG) ? 0 : s + 1;
        }

        // ---- Z: reduce over 4 j-chunk lanes, publish ----
        z0 += __shfl_xor_sync(0xffffffffu, z0, 1);
        z0 += __shfl_xor_sync(0xffffffffu, z0, 2);
        z1 += __shfl_xor_sync(0xffffffffu, z1, 1);
        z1 += __shfl_xor_sync(0xffffffffu, z1, 2);
        if ((lane & 3) == 0) { zsm[r0] = z0; zsm[r0 + 1] = z1; }
        BAR_ARRIVE(7);                               // Z ready
    } else {
        // ========================= CONSUMER (warps 0-7) =========================
        const int mi = wid & 1, ni = wid >> 1;       // 64m x 32n warp tile, K unsplit
        float acc[4][4][4];
        #pragma unroll
        for (int f = 0; f < 4; f++)
            #pragma unroll
            for (int n8 = 0; n8 < 4; n8++)
                #pragma unroll
                for (int q = 0; q < 4; q++) acc[f][n8][q] = 0.0f;

        uint32_t aoff[4], boff[2];
        #pragma unroll
        for (int f = 0; f < 4; f++)
            aoff[f] = (uint32_t)((mi * 64 + f * 16 + (lane & 15)) * PITCH + (lane >> 4) * 16);
        #pragma unroll
        for (int p = 0; p < 2; p++)
            boff[p] = (uint32_t)((ni * 32 + p * 16 + (lane & 7) + ((lane >> 4) << 3)) * PITCH
                                 + ((lane >> 3) & 1) * 16);

        int s = 0;
        for (int kt = 0; kt < NKT; kt++) {
            BAR_SYNC(1 + s);                          // wait FULL(s)
            const uint32_t Ab = smb + s * STG + A_OFF;
            const uint32_t Bb = smb + s * STG + B_OFF;
            #pragma unroll
            for (int kk = 0; kk < 4; kk++) {          // four k16 steps cover KT=64
                const uint32_t koff = kk * 32;        // 16 fp16 = 32 bytes
                uint32_t af[4][4], bf[4][2];
                #pragma unroll
                for (int f = 0; f < 4; f++)
                    LDM4(af[f][0], af[f][1], af[f][2], af[f][3], Ab + aoff[f] + koff);
                #pragma unroll
                for (int p = 0; p < 2; p++)
                    LDM4(bf[2 * p][0], bf[2 * p][1], bf[2 * p + 1][0], bf[2 * p + 1][1],
                         Bb + boff[p] + koff);
                #pragma unroll
                for (int f = 0; f < 4; f++)
                    #pragma unroll
                    for (int n8 = 0; n8 < 4; n8++)
                        MMA_F16(acc[f][n8], af[f], bf[n8]);
            }
            BAR_ARRIVE(4 + s);                        // FREE(s)
            s = (s + 1 == NSTG) ? 0 : s + 1;
        }

        BAR_SYNC(7);                                  // Z ready (drains zsm STS)

        // ---- epilogue: scale by 1/Z, store ----
        #pragma unroll
        for (int f = 0; f < 4; f++) {
            const int row0 = mi * 64 + f * 16 + (lane >> 2);
            const float zz0 = zsm[row0], zz1 = zsm[row0 + 8];
            const float i0 = (zz0 > 0.0f) ? 1.0f / zz0 : 0.0f;
            const float i1 = (zz1 > 0.0f) ? 1.0f / zz1 : 0.0f;
            const size_t go0 = (size_t)(blockRow + row0) * DDIM;
            const size_t go1 = go0 + (size_t)8 * DDIM;
            #pragma unroll
            for (int n8 = 0; n8 < 4; n8++) {
                const int col = ni * 32 + n8 * 8 + (lane & 3) * 2;
                *(float2*)&out[go0 + col] =
                    make_float2(acc[f][n8][0] * i0, acc[f][n8][1] * i0);
                *(float2*)&out[go1 + col] =
                    make_float2(acc[f][n8][2] * i1, acc[f][n8][3] * i1);
            }
        }
    }
}

// ============================ launch =======================================
extern "C" void kernel_launch(void* const* d_in, const int* in_sizes, int n_in,
                              void* d_out, int out_size) {
    const float* sf = (const float*)d_in[0];   // self_feats      [16384,128] f32
    const float* fn = (const float*)d_in[1];   // features_neighs [4096,128]  f32
    const int*   nm = (const int*)d_in[2];     // neigh_matrix    [16384,4096] i32
    const float* a  = (const float*)d_in[3];   // a [256] f32
    float* out = (float*)d_out;

    prep_scalars<<<(NROWS + MCOLS) / 8, 256>>>(sf, fn, a);
    prep_ut<<<dim3(MCOLS / 256, DDIM), 256>>>(fn);

    cudaFuncSetAttribute(attn_main, cudaFuncAttributeMaxDynamicSharedMemorySize, SMEM_BYTES);
    attn_main<<<NROWS / BI, THREADS, SMEM_BYTES>>>(nm, out);
}

// round 12
// speedup vs baseline: 1.2698x; 1.2698x over previous
#include <cuda_runtime.h>
#include <cuda_fp16.h>
#include <cstdint>

// ============================ problem constants ============================
#define NROWS 16384
#define MCOLS 4096
#define DDIM  128
#define BI    128            // rows per CTA
#define KT    32             // j per pipeline stage
#define NKT   (MCOLS / KT)   // 128 stages
#define THREADS 512          // 8 consumer + 8 producer warps
#define NSTG 5               // ring depth
#define LOOKAHEAD 4          // fetch distance (stages)

// A/B pitch: 32 fp16 (64B) + 16B pad = 80 bytes -> conflict-free ldmatrix
#define PITCH 80
// mask pitch: 32 ints (128B) + 16B pad
#define PITCHM 144

// ring-stage layout (bytes, from 16B-aligned smem base)
#define A_OFF  0             // 128 x 80 = 10240
#define B_OFF  10240         // 128 x 80 = 10240
#define MK_OFF 20480         // 128 x 144 = 18432
#define RE_OFF 38912         // 8 producer-warp copies x 256B = 2048
#define STG    40960         // stage stride
#define ZS_OFF (NSTG * STG)  // 204800: 128 floats
#define SMEM_BYTES (ZS_OFF + 512)

// named barriers: FULL(s)=1+s (1-5), FREE(s)=6+s (6-10), Z-ready=11
#define BAR_SYNC(id)   asm volatile("bar.sync %0, %1;"   :: "r"(id), "r"(THREADS) : "memory")
#define BAR_ARRIVE(id) asm volatile("bar.arrive %0, %1;" :: "r"(id), "r"(THREADS) : "memory")

// ============================ device scratch ===============================
__device__ float g_c[NROWS];    // exp(s_i)
__device__ float g_dd[NROWS];   // exp(0.2 s_i)
__device__ float g_r[MCOLS];    // exp(-0.8 t_j)
__device__ float g_et[MCOLS];   // exp(t_j)
__device__ __half g_UTh[(size_t)DDIM * MCOLS]; // U^T[d][j] = fp16(exp(t_j)*V[j][d])

// ============================ asm helpers ==================================
__device__ __forceinline__ uint32_t smem_to_u32(const void* p) {
    uint32_t a;
    asm("{ .reg .u64 t; cvta.to.shared.u64 t, %1; cvt.u32.u64 %0, t; }"
        : "=r"(a) : "l"(p));
    return a;
}

#define LDM4(r0, r1, r2, r3, addr) \
    asm volatile("ldmatrix.sync.aligned.m8n8.x4.shared.b16 {%0,%1,%2,%3}, [%4];" \
        : "=r"(r0), "=r"(r1), "=r"(r2), "=r"(r3) : "r"(addr))

#define MMA_F16(d, a, b) \
    asm volatile("mma.sync.aligned.m16n8k16.row.col.f32.f16.f16.f32 " \
        "{%0,%1,%2,%3}, {%4,%5,%6,%7}, {%8,%9}, {%0,%1,%2,%3};" \
        : "+f"((d)[0]), "+f"((d)[1]), "+f"((d)[2]), "+f"((d)[3]) \
        : "r"((a)[0]), "r"((a)[1]), "r"((a)[2]), "r"((a)[3]), \
          "r"((b)[0]), "r"((b)[1]))

#define CP_ASYNC16(dst, src) \
    asm volatile("cp.async.cg.shared.global [%0], [%1], 16;" :: "r"(dst), "l"(src))
#define CP_COMMIT()  asm volatile("cp.async.commit_group;" ::: "memory")
#define CP_WAIT3()   asm volatile("cp.async.wait_group 3;" ::: "memory")

// ============================ prep kernels =================================
// fused: rows [0,NROWS) -> self scalars, rows [NROWS,NROWS+MCOLS) -> neigh
__global__ void prep_scalars(const float* __restrict__ sf,
                             const float* __restrict__ fn,
                             const float* __restrict__ a) {
    int row = blockIdx.x * 8 + (threadIdx.x >> 5);
    int lane = threadIdx.x & 31;
    const bool is_self = row < NROWS;
    const float* src = is_self ? &sf[(size_t)row * DDIM]
                               : &fn[(size_t)(row - NROWS) * DDIM];
    const float* w   = is_self ? a : a + DDIM;
    float4 f = *(const float4*)&src[lane * 4];
    float4 ww = *(const float4*)&w[lane * 4];
    float v = f.x * ww.x + f.y * ww.y + f.z * ww.z + f.w * ww.w;
    #pragma unroll
    for (int o = 16; o > 0; o >>= 1) v += __shfl_xor_sync(0xffffffffu, v, o);
    if (lane == 0) {
        if (is_self) {
            g_c[row]  = expf(v);
            g_dd[row] = expf(0.2f * v);
        } else {
            int j = row - NROWS;
            g_r[j]  = expf(-0.8f * v);
            g_et[j] = expf(v);
        }
    }
}

__global__ void prep_ut(const float* __restrict__ fn) {
    int j = blockIdx.x * 256 + threadIdx.x;
    int d = blockIdx.y;
    float v = g_et[j] * fn[(size_t)j * DDIM + d];
    g_UTh[(size_t)d * MCOLS + j] = __float2half_rn(v);
}

// ============================ main kernel ==================================
// A = mask ? max(c_i, dd_i * r_j) : 0   (leaky branch: s+t>0 <=> c > dd*r).
// Stored fp16 RN; Z accumulated in f32 (RN rounding is unbiased -> consistent).
__device__ __forceinline__ float aval(int m, float rr, float cc, float dd) {
    float v = fmaxf(cc, dd * rr);
    return m ? v : 0.0f;
}

// fetch one stage: masks for this thread's OWN build rows/cols (so completion
// is visible to this thread after wait_group, no barrier), B tile, RE consts.
__device__ __forceinline__ void fetch_stage(uint32_t smb,
                                            const char* mrow0, const char* mrow1,
                                            const __half* brow, int kt, int s,
                                            int r0, int jc, int frow, int fh,
                                            int pw, int lane) {
    const uint32_t base = smb + s * STG;
    // masks: rows r0, r0+1; 8 j's (32B) at column chunk jc
    uint32_t mdst = base + MK_OFF + r0 * PITCHM + jc * 32u;
    const char* ms0 = mrow0 + (size_t)kt * 128 + jc * 32;
    const char* ms1 = mrow1 + (size_t)kt * 128 + jc * 32;
    CP_ASYNC16(mdst,               ms0);
    CP_ASYNC16(mdst + 16,          ms0 + 16);
    CP_ASYNC16(mdst + PITCHM,      ms1);
    CP_ASYNC16(mdst + PITCHM + 16, ms1 + 16);
    // B: U^T d-row frow, 16-j half fh
    uint32_t bdst = base + B_OFF + frow * PITCH + fh * 32u;
    const __half* bsrc = brow + kt * KT;   // brow already offset by fh*16
    CP_ASYNC16(bdst,      bsrc);
    CP_ASYNC16(bdst + 16, bsrc + 8);
    // r, e consts: per-producer-warp copy
    if (lane < 16) {
        const float* cbase = (lane < 8) ? g_r : g_et;
        const int q = lane & 7;
        CP_ASYNC16(base + RE_OFF + pw * 256u + (lane < 8 ? 0u : 128u) + q * 16u,
                   cbase + kt * KT + q * 4);
    }
}

__global__ void __launch_bounds__(THREADS, 1)
attn_main(const int* __restrict__ nm, float* __restrict__ out) {
    extern __shared__ char sm[];
    const uint32_t smb = smem_to_u32(sm);
    const int tid = threadIdx.x, lane = tid & 31, wid = tid >> 5;
    const int blockRow = blockIdx.x * BI;
    float* zsm = (float*)(sm + ZS_OFF);

    if (wid >= 8) {
        // ========================= PRODUCER (warps 8-15) =========================
        const int tp = tid - 256;
        const int pw = tp >> 5;                    // producer warp 0-7
        const int frow = tp >> 1, fh = tp & 1;     // B fetch: d-row, 16-j half
        const int r0 = (tp >> 2) * 2, jc = tp & 3; // rows r0,r0+1; j-chunk jc (8 j)
        const float cc0 = g_c[blockRow + r0],  cc1 = g_c[blockRow + r0 + 1];
        const float dd0 = g_dd[blockRow + r0], dd1 = g_dd[blockRow + r0 + 1];
        float z0 = 0.0f, z1 = 0.0f;

        const char* mrow0 = (const char*)(nm + (size_t)(blockRow + r0) * MCOLS);
        const char* mrow1 = (const char*)(nm + (size_t)(blockRow + r0 + 1) * MCOLS);
        const __half* brow = g_UTh + (size_t)frow * MCOLS + fh * 16;

        // prologue: stage LOOKAHEAD stages (one commit group per stage)
        #pragma unroll
        for (int k0 = 0; k0 < LOOKAHEAD; k0++) {
            fetch_stage(smb, mrow0, mrow1, brow, k0, k0, r0, jc, frow, fh, pw, lane);
            CP_COMMIT();
        }

        int s = 0;
        for (int kt = 0; kt < NKT; kt++) {
            // commit #kt carries fetch(kt); allowing 3 newest outstanding
            // guarantees fetch(kt) (and everything older) is complete.
            CP_WAIT3();
            __syncwarp();   // publish this warp's RE copy across its lanes

            // ---- build A(kt) into slot s from smem masks (own fetches) ----
            {
                const float4* re = (const float4*)(sm + s * STG + RE_OFF + pw * 256);
                const float4 ra = re[jc * 2],     rb = re[jc * 2 + 1];
                const float4 ea = re[8 + jc * 2], eb = re[8 + jc * 2 + 1];
                const char* mks = sm + s * STG + MK_OFF + r0 * PITCHM + jc * 32;
                char* dst = sm + s * STG + A_OFF + r0 * PITCH + jc * 16;
                #pragma unroll
                for (int i = 0; i < 2; i++) {
                    const int4 ma = *(const int4*)(mks + i * PITCHM);
                    const int4 mb = *(const int4*)(mks + i * PITCHM + 16);
                    const float cc = i ? cc1 : cc0, dd = i ? dd1 : dd0;
                    float a0 = aval(ma.x, ra.x, cc, dd);
                    float a1 = aval(ma.y, ra.y, cc, dd);
                    float a2 = aval(ma.z, ra.z, cc, dd);
                    float a3 = aval(ma.w, ra.w, cc, dd);
                    float a4 = aval(mb.x, rb.x, cc, dd);
                    float a5 = aval(mb.y, rb.y, cc, dd);
                    float a6 = aval(mb.z, rb.z, cc, dd);
                    float a7 = aval(mb.w, rb.w, cc, dd);
                    float z = a0 * ea.x + a1 * ea.y + a2 * ea.z + a3 * ea.w
                            + a4 * eb.x + a5 * eb.y + a6 * eb.z + a7 * eb.w;
                    if (i) z1 += z; else z0 += z;
                    __half2 h0 = __floats2half2_rn(a0, a1);
                    __half2 h1 = __floats2half2_rn(a2, a3);
                    __half2 h2 = __floats2half2_rn(a4, a5);
                    __half2 h3 = __floats2half2_rn(a6, a7);
                    uint4 q;
                    q.x = *(uint32_t*)&h0; q.y = *(uint32_t*)&h1;
                    q.z = *(uint32_t*)&h2; q.w = *(uint32_t*)&h3;
                    *(uint4*)(dst + i * PITCH) = q;
                }
            }
            BAR_ARRIVE(1 + s);                       // FULL(s)

            const int kf = kt + LOOKAHEAD;
            if (kf < NKT) {
                int s4 = s + LOOKAHEAD; if (s4 >= NSTG) s4 -= NSTG;
                if (kf >= NSTG) BAR_SYNC(6 + s4);    // consumers freed slot s4
                fetch_stage(smb, mrow0, mrow1, brow, kf, s4, r0, jc, frow, fh, pw, lane);
            }
            CP_COMMIT();                             // one group per stage, always
            s = (s + 1 == NSTG) ? 0 : s + 1;
        }

        // ---- Z: reduce over 4 j-chunk lanes, publish ----
        z0 += __shfl_xor_sync(0xffffffffu, z0, 1);
        z0 += __shfl_xor_sync(0xffffffffu, z0, 2);
        z1 += __shfl_xor_sync(0xffffffffu, z1, 1);
        z1 += __shfl_xor_sync(0xffffffffu, z1, 2);
        if ((lane & 3) == 0) { zsm[r0] = z0; zsm[r0 + 1] = z1; }
        BAR_ARRIVE(11);                              // Z ready
    } else {
        // ========================= CONSUMER (warps 0-7) =========================
        const int mi = wid & 1, ni = wid >> 1;       // 64m x 32n warp tile, K unsplit
        float acc[4][4][4];
        #pragma unroll
        for (int f = 0; f < 4; f++)
            #pragma unroll
            for (int n8 = 0; n8 < 4; n8++)
                #pragma unroll
                for (int q = 0; q < 4; q++) acc[f][n8][q] = 0.0f;

        uint32_t aoff[4], boff[2];
        #pragma unroll
        for (int f = 0; f < 4; f++)
            aoff[f] = (uint32_t)((mi * 64 + f * 16 + (lane & 15)) * PITCH + (lane >> 4) * 16);
        #pragma unroll
        for (int p = 0; p < 2; p++)
            boff[p] = (uint32_t)((ni * 32 + p * 16 + (lane & 7) + ((lane >> 4) << 3)) * PITCH
                                 + ((lane >> 3) & 1) * 16);

        int s = 0;
        for (int kt = 0; kt < NKT; kt++) {
            BAR_SYNC(1 + s);                          // wait FULL(s)
            const uint32_t Ab = smb + s * STG + A_OFF;
            const uint32_t Bb = smb + s * STG + B_OFF;
            #pragma unroll
            for (int kk = 0; kk < 2; kk++) {          // two k16 steps cover KT=32
                const uint32_t koff = kk * 32;        // 16 fp16 = 32 bytes
                uint32_t af[4][4], bf[4][2];
                #pragma unroll
                for (int f = 0; f < 4; f++)
                    LDM4(af[f][0], af[f][1], af[f][2], af[f][3], Ab + aoff[f] + koff);
                #pragma unroll
                for (int p = 0; p < 2; p++)
                    LDM4(bf[2 * p][0], bf[2 * p][1], bf[2 * p + 1][0], bf[2 * p + 1][1],
                         Bb + boff[p] + koff);
                #pragma unroll
                for (int f = 0; f < 4; f++)
                    #pragma unroll
                    for (int n8 = 0; n8 < 4; n8++)
                        MMA_F16(acc[f][n8], af[f], bf[n8]);
            }
            BAR_ARRIVE(6 + s);                        // FREE(s)
            s = (s + 1 == NSTG) ? 0 : s + 1;
        }

        BAR_SYNC(11);                                 // Z ready (drains zsm STS)

        // ---- epilogue: scale by 1/Z, store ----
        #pragma unroll
        for (int f = 0; f < 4; f++) {
            const int row0 = mi * 64 + f * 16 + (lane >> 2);
            const float zz0 = zsm[row0], zz1 = zsm[row0 + 8];
            const float i0 = (zz0 > 0.0f) ? 1.0f / zz0 : 0.0f;
            const float i1 = (zz1 > 0.0f) ? 1.0f / zz1 : 0.0f;
            const size_t go0 = (size_t)(blockRow + row0) * DDIM;
            const size_t go1 = go0 + (size_t)8 * DDIM;
            #pragma unroll
            for (int n8 = 0; n8 < 4; n8++) {
                const int col = ni * 32 + n8 * 8 + (lane & 3) * 2;
                *(float2*)&out[go0 + col] =
                    make_float2(acc[f][n8][0] * i0, acc[f][n8][1] * i0);
                *(float2*)&out[go1 + col] =
                    make_float2(acc[f][n8][2] * i1, acc[f][n8][3] * i1);
            }
        }
    }
}

// ============================ launch =======================================
extern "C" void kernel_launch(void* const* d_in, const int* in_sizes, int n_in,
                              void* d_out, int out_size) {
    const float* sf = (const float*)d_in[0];   // self_feats      [16384,128] f32
    const float* fn = (const float*)d_in[1];   // features_neighs [4096,128]  f32
    const int*   nm = (const int*)d_in[2];     // neigh_matrix    [16384,4096] i32
    const float* a  = (const float*)d_in[3];   // a [256] f32
    float* out = (float*)d_out;

    prep_scalars<<<(NROWS + MCOLS) / 8, 256>>>(sf, fn, a);
    prep_ut<<<dim3(MCOLS / 256, DDIM), 256>>>(fn);

    cudaFuncSetAttribute(attn_main, cudaFuncAttributeMaxDynamicSharedMemorySize, SMEM_BYTES);
    attn_main<<<NROWS / BI, THREADS, SMEM_BYTES>>>(nm, out);
}